// round 4
// baseline (speedup 1.0000x reference)
#include <cuda_runtime.h>
#include <cuda_bf16.h>
#include <math.h>

// ---------------------------------------------------------------------------
// DLRM forward, fp32 baseline.
//   bottom MLP: 13 -> 512 -> 256 -> 64 (relu)
//   embed: 26 tables x (B,4) gather, mean over 4  -> ly[26][64]
//   interact: T=[x; ly] (27x64), Z=T T^T, tril(-1) -> 351, R=[x|Z] (415)
//   top MLP: 415 -> 512 -> 256 -> 1
// NOTE: lS_i / lS_o are int32 (JAX x64 disabled -> .astype(int64) is a no-op
// down to int32 on save).
// ---------------------------------------------------------------------------

#define B_SZ     8192
#define N_TAB    26
#define D_EMB    64
#define POOL_L   4
#define NFEAT    27              // 1 + N_TAB
#define NPAIR    351             // 27*26/2
#define RDIM     415             // 64 + 351

// scratch (device globals: no allocation allowed)
__device__ float g_buf0[B_SZ * 512];
__device__ float g_buf1[B_SZ * 512];
__device__ float g_R[B_SZ * RDIM];

// ---------------------------------------------------------------------------
// Tiled GEMM: C[M,N] = act(A[M,K] @ W[N,K]^T + bias[N])
// BM=BN=64, BK=16, 256 threads, 4x4 microtile per thread.
// ---------------------------------------------------------------------------
#define BM 64
#define BN 64
#define BK 16
#define TM 4
#define TN 4

template <bool RELU>
__global__ __launch_bounds__(256) void gemm_bias(
    const float* __restrict__ A, const float* __restrict__ W,
    const float* __restrict__ bias, float* __restrict__ C,
    int M, int N, int K)
{
    __shared__ float As[BM][BK + 1];
    __shared__ float Ws[BN][BK + 1];

    const int tid = threadIdx.x;
    const int block_m = blockIdx.y * BM;
    const int block_n = blockIdx.x * BN;
    const int tm = (tid / 16) * TM;   // 0..60
    const int tn = (tid % 16) * TN;   // 0..60

    float acc[TM][TN];
#pragma unroll
    for (int i = 0; i < TM; i++)
#pragma unroll
        for (int j = 0; j < TN; j++) acc[i][j] = 0.f;

    const int kq = tid % BK;          // 0..15  (coalesced k)
    const int mq = tid / BK;          // 0..15

    for (int k0 = 0; k0 < K; k0 += BK) {
        // load A tile (BM x BK): 4 rows per thread, coalesced over k
#pragma unroll
        for (int r = 0; r < BM / 16; r++) {
            int m = mq + r * 16;
            float v = 0.f;
            int k = k0 + kq;
            if (k < K) v = A[(size_t)(block_m + m) * K + k];
            As[m][kq] = v;
        }
        // load W tile (BN x BK)
#pragma unroll
        for (int r = 0; r < BN / 16; r++) {
            int n = mq + r * 16;
            float v = 0.f;
            int k = k0 + kq;
            if (k < K) v = W[(size_t)(block_n + n) * K + k];
            Ws[n][kq] = v;
        }
        __syncthreads();

#pragma unroll
        for (int k = 0; k < BK; k++) {
            float a[TM], w[TN];
#pragma unroll
            for (int i = 0; i < TM; i++) a[i] = As[tm + i][k];
#pragma unroll
            for (int j = 0; j < TN; j++) w[j] = Ws[tn + j][k];
#pragma unroll
            for (int i = 0; i < TM; i++)
#pragma unroll
                for (int j = 0; j < TN; j++) acc[i][j] += a[i] * w[j];
        }
        __syncthreads();
    }

#pragma unroll
    for (int i = 0; i < TM; i++) {
        int m = block_m + tm + i;
#pragma unroll
        for (int j = 0; j < TN; j++) {
            int n = block_n + tn + j;
            float v = acc[i][j] + bias[n];
            if (RELU) v = fmaxf(v, 0.f);
            C[(size_t)m * N + n] = v;
        }
    }
}

// ---------------------------------------------------------------------------
// Embedding gather (mean over L=4) + pairwise-dot interaction.
// One block per batch row. T in shared, stride 65 to avoid bank conflicts.
// R[b] = [ x3[b] (64) | tril dots (351) ]
// ---------------------------------------------------------------------------
__global__ __launch_bounds__(256) void embed_interact(
    const float* __restrict__ x3,          // [B,64]
    const int* __restrict__ lS_i,          // [26, B*4] int32
    const float* __restrict__ tables,      // [26, 100001, 64]
    float* __restrict__ R)                 // [B, 415]
{
    __shared__ float T[NFEAT][D_EMB + 1];
    const int b = blockIdx.x;
    const int tid = threadIdx.x;

    if (tid < D_EMB) T[0][tid] = x3[(size_t)b * D_EMB + tid];

    for (int i = tid; i < N_TAB * D_EMB; i += blockDim.x) {
        int t = i >> 6;
        int d = i & 63;
        const int* idx = lS_i + (size_t)t * (B_SZ * POOL_L) + (size_t)b * POOL_L;
        const float* tab = tables + (size_t)t * 100001 * D_EMB;
        float acc = 0.f;
#pragma unroll
        for (int l = 0; l < POOL_L; l++)
            acc += tab[(size_t)idx[l] * D_EMB + d];
        T[t + 1][d] = acc * 0.25f;
    }
    __syncthreads();

    float* Rb = R + (size_t)b * RDIM;
    if (tid < D_EMB) Rb[tid] = T[0][tid];

    for (int p = tid; p < NPAIR; p += blockDim.x) {
        // p -> (i,j), i>j, row-major tril order
        int i = (int)((1.0f + sqrtf(1.0f + 8.0f * (float)p)) * 0.5f);
        while (i * (i - 1) / 2 > p) i--;
        while ((i + 1) * i / 2 <= p) i++;
        int j = p - i * (i - 1) / 2;

        float acc = 0.f;
#pragma unroll
        for (int d = 0; d < D_EMB; d++) acc += T[i][d] * T[j][d];
        Rb[D_EMB + p] = acc;
    }
}

// ---------------------------------------------------------------------------
// Final layer: out[m] = Z[m,:256] . w2 + b2   (one warp per row)
// ---------------------------------------------------------------------------
__global__ __launch_bounds__(256) void final_layer(
    const float* __restrict__ Z, const float* __restrict__ w,
    const float* __restrict__ bias, float* __restrict__ out, int M, int K)
{
    int warp = (blockIdx.x * blockDim.x + threadIdx.x) >> 5;
    int lane = threadIdx.x & 31;
    if (warp >= M) return;
    float acc = 0.f;
    for (int k = lane; k < K; k += 32)
        acc += Z[(size_t)warp * K + k] * w[k];
#pragma unroll
    for (int o = 16; o; o >>= 1) acc += __shfl_xor_sync(0xFFFFFFFFu, acc, o);
    if (lane == 0) out[warp] = acc + bias[0];
}

// ---------------------------------------------------------------------------
extern "C" void kernel_launch(void* const* d_in, const int* in_sizes, int n_in,
                              void* d_out, int out_size)
{
    (void)in_sizes; (void)n_in; (void)out_size;

    const float* dense_x = (const float*)d_in[0];
    // d_in[1] = lS_o (unused: offsets are b*L by construction)
    const int*   lS_i    = (const int*)d_in[2];
    const float* emb     = (const float*)d_in[3];
    const float* bw0     = (const float*)d_in[4];
    const float* bb0     = (const float*)d_in[5];
    const float* bw1     = (const float*)d_in[6];
    const float* bb1     = (const float*)d_in[7];
    const float* bw2     = (const float*)d_in[8];
    const float* bb2     = (const float*)d_in[9];
    const float* tw0     = (const float*)d_in[10];
    const float* tb0     = (const float*)d_in[11];
    const float* tw1     = (const float*)d_in[12];
    const float* tb1     = (const float*)d_in[13];
    const float* tw2     = (const float*)d_in[14];
    const float* tb2     = (const float*)d_in[15];
    float*       out     = (float*)d_out;

    float *buf0, *buf1, *R;
    cudaGetSymbolAddress((void**)&buf0, g_buf0);
    cudaGetSymbolAddress((void**)&buf1, g_buf1);
    cudaGetSymbolAddress((void**)&R,    g_R);

    dim3 blk(256);
    // bottom MLP
    gemm_bias<true><<<dim3(512 / BN, B_SZ / BM), blk>>>(dense_x, bw0, bb0, buf0, B_SZ, 512, 13);
    gemm_bias<true><<<dim3(256 / BN, B_SZ / BM), blk>>>(buf0,    bw1, bb1, buf1, B_SZ, 256, 512);
    gemm_bias<true><<<dim3( 64 / BN, B_SZ / BM), blk>>>(buf1,    bw2, bb2, buf0, B_SZ,  64, 256);

    // embeddings + interaction -> R[B,415]
    embed_interact<<<B_SZ, blk>>>(buf0, lS_i, emb, R);

    // top MLP
    gemm_bias<true><<<dim3(512 / BN, B_SZ / BM), blk>>>(R,    tw0, tb0, buf1, B_SZ, 512, RDIM);
    gemm_bias<true><<<dim3(256 / BN, B_SZ / BM), blk>>>(buf1, tw1, tb1, buf0, B_SZ, 256, 512);

    // final 256 -> 1
    final_layer<<<(B_SZ * 32 + 255) / 256, blk>>>(buf0, tw2, tb2, out, B_SZ, 256);
}

// round 6
// speedup vs baseline: 1.7832x; 1.7832x over previous
#include <cuda_runtime.h>
#include <cuda_bf16.h>
#include <math.h>
#include <stdint.h>

// ---------------------------------------------------------------------------
// DLRM forward.  TF32 tensor-core GEMMs + vectorized gather/interaction.
//   bottom MLP: 13 -> 512 -> 256 -> 64 (relu)
//   embed: 26 tables x (B,4) gather, mean over 4 -> ly[26][64]
//   interact: T=[x; ly] (27x64), Z=T T^T, tril(-1) -> 351, R=[x|Z] (415)
//   top MLP: 415 -> 512 -> 256 -> 1
// lS_i is int32 (JAX x64 disabled).
// ---------------------------------------------------------------------------

#define B_SZ     8192
#define N_TAB    26
#define D_EMB    64
#define POOL_L   4
#define NFEAT    27
#define NPAIR    351
#define RDIM     415
#define RSTRIDE  416             // padded row stride for R (float4-aligned)

__device__ float g_buf0[B_SZ * 512];
__device__ float g_buf1[B_SZ * 512];
__device__ float g_R[B_SZ * RSTRIDE];

// ===========================================================================
// fp32 GEMM (kept for layer 1, K=13): C = relu(A W^T + b)
// ===========================================================================
#define BM 64
#define BN 64
#define BK 16
#define TM 4
#define TN 4

template <bool RELU>
__global__ __launch_bounds__(256) void gemm_bias(
    const float* __restrict__ A, const float* __restrict__ W,
    const float* __restrict__ bias, float* __restrict__ C,
    int M, int N, int K)
{
    __shared__ float As[BM][BK + 1];
    __shared__ float Ws[BN][BK + 1];

    const int tid = threadIdx.x;
    const int block_m = blockIdx.y * BM;
    const int block_n = blockIdx.x * BN;
    const int tm = (tid / 16) * TM;
    const int tn = (tid % 16) * TN;

    float acc[TM][TN];
#pragma unroll
    for (int i = 0; i < TM; i++)
#pragma unroll
        for (int j = 0; j < TN; j++) acc[i][j] = 0.f;

    const int kq = tid % BK;
    const int mq = tid / BK;

    for (int k0 = 0; k0 < K; k0 += BK) {
#pragma unroll
        for (int r = 0; r < BM / 16; r++) {
            int m = mq + r * 16;
            float v = 0.f;
            int k = k0 + kq;
            if (k < K) v = A[(size_t)(block_m + m) * K + k];
            As[m][kq] = v;
        }
#pragma unroll
        for (int r = 0; r < BN / 16; r++) {
            int n = mq + r * 16;
            float v = 0.f;
            int k = k0 + kq;
            if (k < K) v = W[(size_t)(block_n + n) * K + k];
            Ws[n][kq] = v;
        }
        __syncthreads();

#pragma unroll
        for (int k = 0; k < BK; k++) {
            float a[TM], w[TN];
#pragma unroll
            for (int i = 0; i < TM; i++) a[i] = As[tm + i][k];
#pragma unroll
            for (int j = 0; j < TN; j++) w[j] = Ws[tn + j][k];
#pragma unroll
            for (int i = 0; i < TM; i++)
#pragma unroll
                for (int j = 0; j < TN; j++) acc[i][j] += a[i] * w[j];
        }
        __syncthreads();
    }

#pragma unroll
    for (int i = 0; i < TM; i++) {
        int m = block_m + tm + i;
#pragma unroll
        for (int j = 0; j < TN; j++) {
            int n = block_n + tn + j;
            float v = acc[i][j] + bias[n];
            if (RELU) v = fmaxf(v, 0.f);
            C[(size_t)m * N + n] = v;
        }
    }
}

// ===========================================================================
// TF32 tensor-core GEMM: C[M,N] = relu(A[M,(lda)] @ W[N,K]^T + bias)
// Block tile 128x64, 8 warps (4x2), warp tile 32x32, K-chunk 32.
// mma.sync.m16n8k8.tf32. SMEM rows padded to 36 (conflict-free frag loads).
// VECB: float4 loads of W (requires K%4==0 alignment); else scalar.
// A requires lda%4==0 and tail cols up to next mult of 32... guaranteed by
// caller: K==lda exact multiple of 32, or (K=415, lda=416 with pad zeroed).
// ===========================================================================
#define GTM 128
#define GTN 64
#define GTK 32
#define SPAD 36

__device__ __forceinline__ uint32_t f2tf32(float f) {
    uint32_t r;
    asm("cvt.rna.tf32.f32 %0, %1;" : "=r"(r) : "f"(f));
    return r;
}

template <bool RELU, bool VECB>
__global__ __launch_bounds__(256) void gemm_tf32(
    const float* __restrict__ A, const float* __restrict__ W,
    const float* __restrict__ bias, float* __restrict__ C,
    int M, int N, int K, int lda)
{
    __shared__ uint32_t As[GTM][SPAD];
    __shared__ uint32_t Bs[GTN][SPAD];

    const int tid  = threadIdx.x;
    const int lane = tid & 31;
    const int warp = tid >> 5;
    const int bm = blockIdx.y * GTM;
    const int bn = blockIdx.x * GTN;
    const int warp_m = (warp & 3) * 32;
    const int warp_n = (warp >> 2) * 32;
    const int g  = lane >> 2;      // group id 0..7
    const int tg = lane & 3;       // thread-in-group 0..3

    float acc[2][4][4];
#pragma unroll
    for (int mi = 0; mi < 2; mi++)
#pragma unroll
        for (int ni = 0; ni < 4; ni++)
#pragma unroll
            for (int r = 0; r < 4; r++) acc[mi][ni][r] = 0.f;

    const int nch = (K + GTK - 1) / GTK;

    for (int ch = 0; ch < nch; ch++) {
        const int k0 = ch * GTK;

        // ---- load A tile 128x32 as float4 (alignment guaranteed by caller)
#pragma unroll
        for (int it = 0; it < 4; it++) {
            int idx = tid + it * 256;        // 0..1023
            int row = idx >> 3;              // 0..127
            int c4  = (idx & 7) * 4;         // 0,4,...,28
            float4 v = *reinterpret_cast<const float4*>(
                A + (size_t)(bm + row) * lda + k0 + c4);
            As[row][c4 + 0] = f2tf32(v.x);
            As[row][c4 + 1] = f2tf32(v.y);
            As[row][c4 + 2] = f2tf32(v.z);
            As[row][c4 + 3] = f2tf32(v.w);
        }
        // ---- load B tile 64x32
        if (VECB) {
#pragma unroll
            for (int it = 0; it < 2; it++) {
                int idx = tid + it * 256;    // 0..511
                int row = idx >> 3;          // 0..63
                int c4  = (idx & 7) * 4;
                float4 v = *reinterpret_cast<const float4*>(
                    W + (size_t)(bn + row) * K + k0 + c4);
                Bs[row][c4 + 0] = f2tf32(v.x);
                Bs[row][c4 + 1] = f2tf32(v.y);
                Bs[row][c4 + 2] = f2tf32(v.z);
                Bs[row][c4 + 3] = f2tf32(v.w);
            }
        } else {
#pragma unroll
            for (int it = 0; it < 8; it++) {
                int idx = tid + it * 256;    // 0..2047
                int row = idx >> 5;          // 0..63
                int k   = idx & 31;
                float v = 0.f;
                if (k0 + k < K) v = W[(size_t)(bn + row) * K + k0 + k];
                Bs[row][k] = f2tf32(v);
            }
        }
        __syncthreads();

#pragma unroll
        for (int ks = 0; ks < 4; ks++) {
            const int k = ks * 8;
            uint32_t af[2][4], bf[4][2];
#pragma unroll
            for (int mi = 0; mi < 2; mi++) {
                int r = warp_m + mi * 16 + g;
                af[mi][0] = As[r    ][k + tg];
                af[mi][1] = As[r + 8][k + tg];
                af[mi][2] = As[r    ][k + 4 + tg];
                af[mi][3] = As[r + 8][k + 4 + tg];
            }
#pragma unroll
            for (int ni = 0; ni < 4; ni++) {
                int c = warp_n + ni * 8 + g;
                bf[ni][0] = Bs[c][k + tg];
                bf[ni][1] = Bs[c][k + 4 + tg];
            }
#pragma unroll
            for (int mi = 0; mi < 2; mi++)
#pragma unroll
                for (int ni = 0; ni < 4; ni++) {
                    asm volatile(
                        "mma.sync.aligned.m16n8k8.row.col.f32.tf32.tf32.f32 "
                        "{%0,%1,%2,%3}, {%4,%5,%6,%7}, {%8,%9}, {%0,%1,%2,%3};"
                        : "+f"(acc[mi][ni][0]), "+f"(acc[mi][ni][1]),
                          "+f"(acc[mi][ni][2]), "+f"(acc[mi][ni][3])
                        : "r"(af[mi][0]), "r"(af[mi][1]),
                          "r"(af[mi][2]), "r"(af[mi][3]),
                          "r"(bf[ni][0]), "r"(bf[ni][1]));
                }
        }
        __syncthreads();
    }

    // ---- epilogue
#pragma unroll
    for (int mi = 0; mi < 2; mi++) {
#pragma unroll
        for (int ni = 0; ni < 4; ni++) {
            int c = bn + warp_n + ni * 8 + tg * 2;
            float b0 = bias[c], b1 = bias[c + 1];
            int r0 = bm + warp_m + mi * 16 + g;
            float v0 = acc[mi][ni][0] + b0;
            float v1 = acc[mi][ni][1] + b1;
            float v2 = acc[mi][ni][2] + b0;
            float v3 = acc[mi][ni][3] + b1;
            if (RELU) {
                v0 = fmaxf(v0, 0.f); v1 = fmaxf(v1, 0.f);
                v2 = fmaxf(v2, 0.f); v3 = fmaxf(v3, 0.f);
            }
            C[(size_t)r0 * N + c]           = v0;
            C[(size_t)r0 * N + c + 1]       = v1;
            C[(size_t)(r0 + 8) * N + c]     = v2;
            C[(size_t)(r0 + 8) * N + c + 1] = v3;
        }
    }
}

// ===========================================================================
// Embedding gather (mean over 4) + pairwise-dot interaction, vectorized.
// T stored [27][68] floats (17 float4 per row) for aligned LDS.128.
// R row stride RSTRIDE=416; pad element zeroed.
// ===========================================================================
__global__ __launch_bounds__(256) void embed_interact(
    const float* __restrict__ x3,          // [B,64]
    const int* __restrict__ lS_i,          // [26, B*4] int32
    const float* __restrict__ tables,      // [26, 100001, 64]
    float* __restrict__ R)                 // [B, RSTRIDE]
{
    __shared__ float T[NFEAT * 68];
    const int b = blockIdx.x;
    const int tid = threadIdx.x;

    // x row -> T[0]
    if (tid < 16) {
        float4 v = *reinterpret_cast<const float4*>(x3 + (size_t)b * D_EMB + tid * 4);
        *reinterpret_cast<float4*>(&T[tid * 4]) = v;
    }

    // gather: 26 tables x 16 float4 columns = 416 work items
    for (int i = tid; i < N_TAB * 16; i += 256) {
        int t  = i >> 4;
        int d4 = (i & 15) * 4;
        int4 idx = *reinterpret_cast<const int4*>(
            lS_i + (size_t)t * (B_SZ * POOL_L) + (size_t)b * POOL_L);
        const float* tab = tables + (size_t)t * 100001 * D_EMB;
        float4 v0 = *reinterpret_cast<const float4*>(tab + (size_t)idx.x * D_EMB + d4);
        float4 v1 = *reinterpret_cast<const float4*>(tab + (size_t)idx.y * D_EMB + d4);
        float4 v2 = *reinterpret_cast<const float4*>(tab + (size_t)idx.z * D_EMB + d4);
        float4 v3 = *reinterpret_cast<const float4*>(tab + (size_t)idx.w * D_EMB + d4);
        float* dst = &T[(t + 1) * 68 + d4];
        dst[0] = (v0.x + v1.x + v2.x + v3.x) * 0.25f;
        dst[1] = (v0.y + v1.y + v2.y + v3.y) * 0.25f;
        dst[2] = (v0.z + v1.z + v2.z + v3.z) * 0.25f;
        dst[3] = (v0.w + v1.w + v2.w + v3.w) * 0.25f;
    }
    __syncthreads();

    float* Rb = R + (size_t)b * RSTRIDE;
    if (tid < 16) {
        *reinterpret_cast<float4*>(Rb + tid * 4) =
            *reinterpret_cast<const float4*>(&T[tid * 4]);
    }
    if (tid == 16) Rb[RDIM] = 0.f;   // zero the pad (K=415 GEMM reads it)

    const float4* T4 = reinterpret_cast<const float4*>(T);  // stride 17 per row

    for (int p = tid; p < NPAIR; p += 256) {
        int i = (int)((1.0f + sqrtf(1.0f + 8.0f * (float)p)) * 0.5f);
        while (i * (i - 1) / 2 > p) i--;
        while ((i + 1) * i / 2 <= p) i++;
        int j = p - i * (i - 1) / 2;

        const float4* ti = T4 + i * 17;
        const float4* tj = T4 + j * 17;
        float acc = 0.f;
#pragma unroll
        for (int d4 = 0; d4 < 16; d4++) {
            float4 u = ti[d4];
            float4 v = tj[d4];
            acc += u.x * v.x + u.y * v.y + u.z * v.z + u.w * v.w;
        }
        Rb[D_EMB + p] = acc;
    }
}

// ===========================================================================
// Final layer: out[m] = Z[m,:256].w + b   (one warp per row)
// ===========================================================================
__global__ __launch_bounds__(256) void final_layer(
    const float* __restrict__ Z, const float* __restrict__ w,
    const float* __restrict__ bias, float* __restrict__ out, int M, int K)
{
    int warp = (blockIdx.x * blockDim.x + threadIdx.x) >> 5;
    int lane = threadIdx.x & 31;
    if (warp >= M) return;
    float acc = 0.f;
    for (int k = lane * 4; k < K; k += 128) {
        float4 z = *reinterpret_cast<const float4*>(Z + (size_t)warp * K + k);
        float4 ww = *reinterpret_cast<const float4*>(w + k);
        acc += z.x * ww.x + z.y * ww.y + z.z * ww.z + z.w * ww.w;
    }
#pragma unroll
    for (int o = 16; o; o >>= 1) acc += __shfl_xor_sync(0xFFFFFFFFu, acc, o);
    if (lane == 0) out[warp] = acc + bias[0];
}

// ===========================================================================
extern "C" void kernel_launch(void* const* d_in, const int* in_sizes, int n_in,
                              void* d_out, int out_size)
{
    (void)in_sizes; (void)n_in; (void)out_size;

    const float* dense_x = (const float*)d_in[0];
    const int*   lS_i    = (const int*)d_in[2];
    const float* emb     = (const float*)d_in[3];
    const float* bw0     = (const float*)d_in[4];
    const float* bb0     = (const float*)d_in[5];
    const float* bw1     = (const float*)d_in[6];
    const float* bb1     = (const float*)d_in[7];
    const float* bw2     = (const float*)d_in[8];
    const float* bb2     = (const float*)d_in[9];
    const float* tw0     = (const float*)d_in[10];
    const float* tb0     = (const float*)d_in[11];
    const float* tw1     = (const float*)d_in[12];
    const float* tb1     = (const float*)d_in[13];
    const float* tw2     = (const float*)d_in[14];
    const float* tb2     = (const float*)d_in[15];
    float*       out     = (float*)d_out;

    float *buf0, *buf1, *R;
    cudaGetSymbolAddress((void**)&buf0, g_buf0);
    cudaGetSymbolAddress((void**)&buf1, g_buf1);
    cudaGetSymbolAddress((void**)&R,    g_R);

    dim3 blk(256);

    // layer 1: 13 -> 512 (fp32, K tiny)
    gemm_bias<true><<<dim3(512 / BN, B_SZ / BM), blk>>>(dense_x, bw0, bb0, buf0, B_SZ, 512, 13);
    // layer 2: 512 -> 256 (tf32)
    gemm_tf32<true, true><<<dim3(256 / GTN, B_SZ / GTM), blk>>>(buf0, bw1, bb1, buf1, B_SZ, 256, 512, 512);
    // layer 3: 256 -> 64 (tf32)
    gemm_tf32<true, true><<<dim3(64 / GTN, B_SZ / GTM), blk>>>(buf1, bw2, bb2, buf0, B_SZ, 64, 256, 256);

    // embeddings + interaction -> R[B,416]
    embed_interact<<<B_SZ, blk>>>(buf0, lS_i, emb, R);

    // layer 4: 415 -> 512 (tf32, A stride 416, scalar W loads)
    gemm_tf32<true, false><<<dim3(512 / GTN, B_SZ / GTM), blk>>>(R, tw0, tb0, buf1, B_SZ, 512, RDIM, RSTRIDE);
    // layer 5: 512 -> 256 (tf32)
    gemm_tf32<true, true><<<dim3(256 / GTN, B_SZ / GTM), blk>>>(buf1, tw1, tb1, buf0, B_SZ, 256, 512, 512);

    // final 256 -> 1
    final_layer<<<(B_SZ * 32 + 255) / 256, blk>>>(buf0, tw2, tb2, out, B_SZ, 256);
}

// round 8
// speedup vs baseline: 2.1725x; 1.2183x over previous
#include <cuda_runtime.h>
#include <cuda_bf16.h>
#include <math.h>
#include <stdint.h>

// ---------------------------------------------------------------------------
// DLRM forward.  TF32 tensor-core GEMMs (reg-prefetch pipelined) +
// multi-row vectorized gather/interaction.
//   bottom MLP: 13 -> 512 -> 256 -> 64 (relu)
//   embed: 26 tables x (B,4) gather, mean over 4 -> ly[26][64]
//   interact: T=[x; ly] (27x64), Z=T T^T, tril(-1) -> 351, R=[x|Z] (415)
//   top MLP: 415 -> 512 -> 256 -> 1
// lS_i is int32 (JAX x64 disabled).
// ---------------------------------------------------------------------------

#define B_SZ     8192
#define N_TAB    26
#define D_EMB    64
#define POOL_L   4
#define NFEAT    27
#define NPAIR    351
#define RDIM     415
#define RSTRIDE  416             // padded row stride for R (float4-aligned)

__device__ float g_buf0[B_SZ * 512];
__device__ float g_buf1[B_SZ * 512];
__device__ float g_R[B_SZ * RSTRIDE];
__device__ float g_w0pad[512 * RSTRIDE];   // tw0 repacked to stride 416, pad=0

// ===========================================================================
// fp32 GEMM (layer 1 only, K=13)
// ===========================================================================
#define BM 64
#define BN 64
#define BK 16
#define TM 4
#define TN 4

template <bool RELU>
__global__ __launch_bounds__(256) void gemm_bias(
    const float* __restrict__ A, const float* __restrict__ W,
    const float* __restrict__ bias, float* __restrict__ C,
    int M, int N, int K)
{
    __shared__ float As[BM][BK + 1];
    __shared__ float Ws[BN][BK + 1];

    const int tid = threadIdx.x;
    const int block_m = blockIdx.y * BM;
    const int block_n = blockIdx.x * BN;
    const int tm = (tid / 16) * TM;
    const int tn = (tid % 16) * TN;

    float acc[TM][TN];
#pragma unroll
    for (int i = 0; i < TM; i++)
#pragma unroll
        for (int j = 0; j < TN; j++) acc[i][j] = 0.f;

    const int kq = tid % BK;
    const int mq = tid / BK;

    for (int k0 = 0; k0 < K; k0 += BK) {
#pragma unroll
        for (int r = 0; r < BM / 16; r++) {
            int m = mq + r * 16;
            float v = 0.f;
            int k = k0 + kq;
            if (k < K) v = A[(size_t)(block_m + m) * K + k];
            As[m][kq] = v;
        }
#pragma unroll
        for (int r = 0; r < BN / 16; r++) {
            int n = mq + r * 16;
            float v = 0.f;
            int k = k0 + kq;
            if (k < K) v = W[(size_t)(block_n + n) * K + k];
            Ws[n][kq] = v;
        }
        __syncthreads();

#pragma unroll
        for (int k = 0; k < BK; k++) {
            float a[TM], w[TN];
#pragma unroll
            for (int i = 0; i < TM; i++) a[i] = As[tm + i][k];
#pragma unroll
            for (int j = 0; j < TN; j++) w[j] = Ws[tn + j][k];
#pragma unroll
            for (int i = 0; i < TM; i++)
#pragma unroll
                for (int j = 0; j < TN; j++) acc[i][j] += a[i] * w[j];
        }
        __syncthreads();
    }

#pragma unroll
    for (int i = 0; i < TM; i++) {
        int m = block_m + tm + i;
#pragma unroll
        for (int j = 0; j < TN; j++) {
            int n = block_n + tn + j;
            float v = acc[i][j] + bias[n];
            if (RELU) v = fmaxf(v, 0.f);
            C[(size_t)m * N + n] = v;
        }
    }
}

// ===========================================================================
// TF32 tensor-core GEMM with register-prefetch pipeline.
// C[M,N] = relu(A[M,(lda)] @ W[N,(ldb)]^T + bias)
// Block 128x64, 8 warps (4x2), warp tile 32x32, K-chunk 32.
// Requires: lda, ldb multiples of 4; K multiple of 32; zero-padding beyond
// the true reduction dim inside [K] guaranteed by caller.
// ===========================================================================
#define GTM 128
#define GTN 64
#define GTK 32
#define SPAD 36

__device__ __forceinline__ uint32_t f2tf32(float f) {
    uint32_t r;
    asm("cvt.rna.tf32.f32 %0, %1;" : "=r"(r) : "f"(f));
    return r;
}

template <bool RELU>
__global__ __launch_bounds__(256) void gemm_tf32(
    const float* __restrict__ A, const float* __restrict__ W,
    const float* __restrict__ bias, float* __restrict__ C,
    int M, int N, int K, int lda, int ldb)
{
    __shared__ uint32_t As[GTM][SPAD];
    __shared__ uint32_t Bs[GTN][SPAD];

    const int tid  = threadIdx.x;
    const int lane = tid & 31;
    const int warp = tid >> 5;
    const int bm = blockIdx.y * GTM;
    const int bn = blockIdx.x * GTN;
    const int warp_m = (warp & 3) * 32;
    const int warp_n = (warp >> 2) * 32;
    const int g  = lane >> 2;
    const int tg = lane & 3;

    // per-thread load coordinates (fixed across chunks)
    const int a_row = tid >> 3;            // 0..31 base; 4 tiles of 32 rows
    const int a_c4  = (tid & 7) * 4;

    float acc[2][4][4];
#pragma unroll
    for (int mi = 0; mi < 2; mi++)
#pragma unroll
        for (int ni = 0; ni < 4; ni++)
#pragma unroll
            for (int r = 0; r < 4; r++) acc[mi][ni][r] = 0.f;

    const int nch = K / GTK;

    float4 pa[4], pb[2];
    // prologue fetch: chunk 0
#pragma unroll
    for (int it = 0; it < 4; it++)
        pa[it] = *reinterpret_cast<const float4*>(
            A + (size_t)(bm + a_row + it * 32) * lda + a_c4);
#pragma unroll
    for (int it = 0; it < 2; it++)
        pb[it] = *reinterpret_cast<const float4*>(
            W + (size_t)(bn + a_row + it * 32) * ldb + a_c4);

    for (int ch = 0; ch < nch; ch++) {
        // ---- store prefetched regs to SMEM (with tf32 convert)
#pragma unroll
        for (int it = 0; it < 4; it++) {
            int row = a_row + it * 32;
            As[row][a_c4 + 0] = f2tf32(pa[it].x);
            As[row][a_c4 + 1] = f2tf32(pa[it].y);
            As[row][a_c4 + 2] = f2tf32(pa[it].z);
            As[row][a_c4 + 3] = f2tf32(pa[it].w);
        }
#pragma unroll
        for (int it = 0; it < 2; it++) {
            int row = a_row + it * 32;
            Bs[row][a_c4 + 0] = f2tf32(pb[it].x);
            Bs[row][a_c4 + 1] = f2tf32(pb[it].y);
            Bs[row][a_c4 + 2] = f2tf32(pb[it].z);
            Bs[row][a_c4 + 3] = f2tf32(pb[it].w);
        }
        __syncthreads();

        // ---- prefetch next chunk into regs (overlaps with MMA below)
        if (ch + 1 < nch) {
            const int k0 = (ch + 1) * GTK;
#pragma unroll
            for (int it = 0; it < 4; it++)
                pa[it] = *reinterpret_cast<const float4*>(
                    A + (size_t)(bm + a_row + it * 32) * lda + k0 + a_c4);
#pragma unroll
            for (int it = 0; it < 2; it++)
                pb[it] = *reinterpret_cast<const float4*>(
                    W + (size_t)(bn + a_row + it * 32) * ldb + k0 + a_c4);
        }

        // ---- compute on SMEM tile
#pragma unroll
        for (int ks = 0; ks < 4; ks++) {
            const int k = ks * 8;
            uint32_t af[2][4], bf[4][2];
#pragma unroll
            for (int mi = 0; mi < 2; mi++) {
                int r = warp_m + mi * 16 + g;
                af[mi][0] = As[r    ][k + tg];
                af[mi][1] = As[r + 8][k + tg];
                af[mi][2] = As[r    ][k + 4 + tg];
                af[mi][3] = As[r + 8][k + 4 + tg];
            }
#pragma unroll
            for (int ni = 0; ni < 4; ni++) {
                int c = warp_n + ni * 8 + g;
                bf[ni][0] = Bs[c][k + tg];
                bf[ni][1] = Bs[c][k + 4 + tg];
            }
#pragma unroll
            for (int mi = 0; mi < 2; mi++)
#pragma unroll
                for (int ni = 0; ni < 4; ni++) {
                    asm volatile(
                        "mma.sync.aligned.m16n8k8.row.col.f32.tf32.tf32.f32 "
                        "{%0,%1,%2,%3}, {%4,%5,%6,%7}, {%8,%9}, {%0,%1,%2,%3};"
                        : "+f"(acc[mi][ni][0]), "+f"(acc[mi][ni][1]),
                          "+f"(acc[mi][ni][2]), "+f"(acc[mi][ni][3])
                        : "r"(af[mi][0]), "r"(af[mi][1]),
                          "r"(af[mi][2]), "r"(af[mi][3]),
                          "r"(bf[ni][0]), "r"(bf[ni][1]));
                }
        }
        __syncthreads();
    }

    // ---- epilogue
#pragma unroll
    for (int mi = 0; mi < 2; mi++) {
#pragma unroll
        for (int ni = 0; ni < 4; ni++) {
            int c = bn + warp_n + ni * 8 + tg * 2;
            float b0 = bias[c], b1 = bias[c + 1];
            int r0 = bm + warp_m + mi * 16 + g;
            float v0 = acc[mi][ni][0] + b0;
            float v1 = acc[mi][ni][1] + b1;
            float v2 = acc[mi][ni][2] + b0;
            float v3 = acc[mi][ni][3] + b1;
            if (RELU) {
                v0 = fmaxf(v0, 0.f); v1 = fmaxf(v1, 0.f);
                v2 = fmaxf(v2, 0.f); v3 = fmaxf(v3, 0.f);
            }
            C[(size_t)r0 * N + c]           = v0;
            C[(size_t)r0 * N + c + 1]       = v1;
            C[(size_t)(r0 + 8) * N + c]     = v2;
            C[(size_t)(r0 + 8) * N + c + 1] = v3;
        }
    }
}

// ===========================================================================
// Repack tw0 [512][415] -> g_w0pad [512][416], pad col = 0
// ===========================================================================
__global__ __launch_bounds__(256) void repack_w0(
    const float* __restrict__ src, float* __restrict__ dst)
{
    int i = blockIdx.x * blockDim.x + threadIdx.x;
    if (i >= 512 * RSTRIDE) return;
    int row = i / RSTRIDE;
    int col = i - row * RSTRIDE;
    dst[i] = (col < RDIM) ? src[(size_t)row * RDIM + col] : 0.f;
}

// ===========================================================================
// Embedding gather (mean over 4) + interaction; 4 batch rows per block.
// T rows stored at stride 68 floats (17 float4) for aligned LDS.128.
// ===========================================================================
#define RPB 4

__global__ __launch_bounds__(256) void embed_interact(
    const float* __restrict__ x3,          // [B,64]
    const int* __restrict__ lS_i,          // [26, B*4] int32
    const float* __restrict__ tables,      // [26, 100001, 64]
    float* __restrict__ R)                 // [B, RSTRIDE]
{
    __shared__ float T[RPB][NFEAT * 68];
    const int b0 = blockIdx.x * RPB;
    const int tid = threadIdx.x;

    // x rows -> T[r][0..63]
    if (tid < RPB * 16) {
        int r = tid >> 4, q = tid & 15;
        float4 v = *reinterpret_cast<const float4*>(
            x3 + (size_t)(b0 + r) * D_EMB + q * 4);
        *reinterpret_cast<float4*>(&T[r][q * 4]) = v;
    }

    // gather: RPB * 26 tables * 16 float4 cols = 1664 items
    for (int i = tid; i < RPB * N_TAB * 16; i += 256) {
        int d4 = (i & 15) * 4;
        int tt = i >> 4;              // 0..103
        int t  = tt % N_TAB;
        int r  = tt / N_TAB;
        int4 idx = *reinterpret_cast<const int4*>(
            lS_i + (size_t)t * (B_SZ * POOL_L) + (size_t)(b0 + r) * POOL_L);
        const float* tab = tables + (size_t)t * 100001 * D_EMB;
        float4 v0 = *reinterpret_cast<const float4*>(tab + (size_t)idx.x * D_EMB + d4);
        float4 v1 = *reinterpret_cast<const float4*>(tab + (size_t)idx.y * D_EMB + d4);
        float4 v2 = *reinterpret_cast<const float4*>(tab + (size_t)idx.z * D_EMB + d4);
        float4 v3 = *reinterpret_cast<const float4*>(tab + (size_t)idx.w * D_EMB + d4);
        float* dst = &T[r][(t + 1) * 68 + d4];
        dst[0] = (v0.x + v1.x + v2.x + v3.x) * 0.25f;
        dst[1] = (v0.y + v1.y + v2.y + v3.y) * 0.25f;
        dst[2] = (v0.z + v1.z + v2.z + v3.z) * 0.25f;
        dst[3] = (v0.w + v1.w + v2.w + v3.w) * 0.25f;
    }
    __syncthreads();

    // copy x to R, zero the pad column
    if (tid < RPB * 16) {
        int r = tid >> 4, q = tid & 15;
        *reinterpret_cast<float4*>(R + (size_t)(b0 + r) * RSTRIDE + q * 4) =
            *reinterpret_cast<const float4*>(&T[r][q * 4]);
    }
    if (tid < RPB) R[(size_t)(b0 + tid) * RSTRIDE + RDIM] = 0.f;

    // pairwise dots: RPB * 351 = 1404 items
    for (int ii = tid; ii < RPB * NPAIR; ii += 256) {
        int r = ii / NPAIR;
        int p = ii - r * NPAIR;
        int i = (int)((1.0f + sqrtf(1.0f + 8.0f * (float)p)) * 0.5f);
        while (i * (i - 1) / 2 > p) i--;
        while ((i + 1) * i / 2 <= p) i++;
        int j = p - i * (i - 1) / 2;

        const float4* ti = reinterpret_cast<const float4*>(&T[r][i * 68]);
        const float4* tj = reinterpret_cast<const float4*>(&T[r][j * 68]);
        float acc = 0.f;
#pragma unroll
        for (int d4 = 0; d4 < 16; d4++) {
            float4 u = ti[d4];
            float4 v = tj[d4];
            acc += u.x * v.x + u.y * v.y + u.z * v.z + u.w * v.w;
        }
        R[(size_t)(b0 + r) * RSTRIDE + D_EMB + p] = acc;
    }
}

// ===========================================================================
// Final layer: out[m] = Z[m,:256].w + b   (one warp per row)
// ===========================================================================
__global__ __launch_bounds__(256) void final_layer(
    const float* __restrict__ Z, const float* __restrict__ w,
    const float* __restrict__ bias, float* __restrict__ out, int M, int K)
{
    int warp = (blockIdx.x * blockDim.x + threadIdx.x) >> 5;
    int lane = threadIdx.x & 31;
    if (warp >= M) return;
    float acc = 0.f;
    for (int k = lane * 4; k < K; k += 128) {
        float4 z = *reinterpret_cast<const float4*>(Z + (size_t)warp * K + k);
        float4 ww = *reinterpret_cast<const float4*>(w + k);
        acc += z.x * ww.x + z.y * ww.y + z.z * ww.z + z.w * ww.w;
    }
#pragma unroll
    for (int o = 16; o; o >>= 1) acc += __shfl_xor_sync(0xFFFFFFFFu, acc, o);
    if (lane == 0) out[warp] = acc + bias[0];
}

// ===========================================================================
extern "C" void kernel_launch(void* const* d_in, const int* in_sizes, int n_in,
                              void* d_out, int out_size)
{
    (void)in_sizes; (void)n_in; (void)out_size;

    const float* dense_x = (const float*)d_in[0];
    const int*   lS_i    = (const int*)d_in[2];
    const float* emb     = (const float*)d_in[3];
    const float* bw0     = (const float*)d_in[4];
    const float* bb0     = (const float*)d_in[5];
    const float* bw1     = (const float*)d_in[6];
    const float* bb1     = (const float*)d_in[7];
    const float* bw2     = (const float*)d_in[8];
    const float* bb2     = (const float*)d_in[9];
    const float* tw0     = (const float*)d_in[10];
    const float* tb0     = (const float*)d_in[11];
    const float* tw1     = (const float*)d_in[12];
    const float* tb1     = (const float*)d_in[13];
    const float* tw2     = (const float*)d_in[14];
    const float* tb2     = (const float*)d_in[15];
    float*       out     = (float*)d_out;

    float *buf0, *buf1, *R, *w0pad;
    cudaGetSymbolAddress((void**)&buf0,  g_buf0);
    cudaGetSymbolAddress((void**)&buf1,  g_buf1);
    cudaGetSymbolAddress((void**)&R,     g_R);
    cudaGetSymbolAddress((void**)&w0pad, g_w0pad);

    dim3 blk(256);

    // repack tw0 early (independent of everything before layer 4)
    repack_w0<<<(512 * RSTRIDE + 255) / 256, blk>>>(tw0, w0pad);

    // layer 1: 13 -> 512 (fp32)
    gemm_bias<true><<<dim3(512 / BN, B_SZ / BM), blk>>>(dense_x, bw0, bb0, buf0, B_SZ, 512, 13);
    // layer 2: 512 -> 256 (tf32)
    gemm_tf32<true><<<dim3(256 / GTN, B_SZ / GTM), blk>>>(buf0, bw1, bb1, buf1, B_SZ, 256, 512, 512, 512);
    // layer 3: 256 -> 64 (tf32)
    gemm_tf32<true><<<dim3(64 / GTN, B_SZ / GTM), blk>>>(buf1, bw2, bb2, buf0, B_SZ, 64, 256, 256, 256);

    // embeddings + interaction -> R[B,416] (pad zeroed)
    embed_interact<<<B_SZ / RPB, blk>>>(buf0, lS_i, emb, R);

    // layer 4: 416 -> 512 (tf32; both operands padded to 416 with zeros)
    gemm_tf32<true><<<dim3(512 / GTN, B_SZ / GTM), blk>>>(R, w0pad, tb0, buf1, B_SZ, 512, RSTRIDE, RSTRIDE, RSTRIDE);
    // layer 5: 512 -> 256 (tf32)
    gemm_tf32<true><<<dim3(256 / GTN, B_SZ / GTM), blk>>>(buf1, tw1, tb1, buf0, B_SZ, 256, 512, 512, 512);

    // final 256 -> 1
    final_layer<<<(B_SZ * 32 + 255) / 256, blk>>>(buf0, tw2, tb2, out, B_SZ, 256);
}

// round 9
// speedup vs baseline: 2.2259x; 1.0246x over previous
#include <cuda_runtime.h>
#include <cuda_bf16.h>
#include <math.h>
#include <stdint.h>

// ---------------------------------------------------------------------------
// DLRM forward.  TF32 tensor-core GEMMs (cp.async 2-stage pipeline) +
// multi-row vectorized gather/interaction.
// lS_i is int32 (JAX x64 disabled).
// ---------------------------------------------------------------------------

#define B_SZ     8192
#define N_TAB    26
#define D_EMB    64
#define POOL_L   4
#define NFEAT    27
#define NPAIR    351
#define RDIM     415
#define RSTRIDE  416

__device__ float g_buf0[B_SZ * 512];
__device__ float g_buf1[B_SZ * 512];
__device__ float g_R[B_SZ * RSTRIDE];
__device__ float g_w0pad[512 * RSTRIDE];

// ===========================================================================
// fp32 GEMM (layer 1 only, K=13)
// ===========================================================================
#define BM 64
#define BN 64
#define BK 16
#define TM 4
#define TN 4

template <bool RELU>
__global__ __launch_bounds__(256) void gemm_bias(
    const float* __restrict__ A, const float* __restrict__ W,
    const float* __restrict__ bias, float* __restrict__ C,
    int M, int N, int K)
{
    __shared__ float As[BM][BK + 1];
    __shared__ float Ws[BN][BK + 1];

    const int tid = threadIdx.x;
    const int block_m = blockIdx.y * BM;
    const int block_n = blockIdx.x * BN;
    const int tm = (tid / 16) * TM;
    const int tn = (tid % 16) * TN;

    float acc[TM][TN];
#pragma unroll
    for (int i = 0; i < TM; i++)
#pragma unroll
        for (int j = 0; j < TN; j++) acc[i][j] = 0.f;

    const int kq = tid % BK;
    const int mq = tid / BK;

    for (int k0 = 0; k0 < K; k0 += BK) {
#pragma unroll
        for (int r = 0; r < BM / 16; r++) {
            int m = mq + r * 16;
            float v = 0.f;
            int k = k0 + kq;
            if (k < K) v = A[(size_t)(block_m + m) * K + k];
            As[m][kq] = v;
        }
#pragma unroll
        for (int r = 0; r < BN / 16; r++) {
            int n = mq + r * 16;
            float v = 0.f;
            int k = k0 + kq;
            if (k < K) v = W[(size_t)(block_n + n) * K + k];
            Ws[n][kq] = v;
        }
        __syncthreads();

#pragma unroll
        for (int k = 0; k < BK; k++) {
            float a[TM], w[TN];
#pragma unroll
            for (int i = 0; i < TM; i++) a[i] = As[tm + i][k];
#pragma unroll
            for (int j = 0; j < TN; j++) w[j] = Ws[tn + j][k];
#pragma unroll
            for (int i = 0; i < TM; i++)
#pragma unroll
                for (int j = 0; j < TN; j++) acc[i][j] += a[i] * w[j];
        }
        __syncthreads();
    }

#pragma unroll
    for (int i = 0; i < TM; i++) {
        int m = block_m + tm + i;
#pragma unroll
        for (int j = 0; j < TN; j++) {
            int n = block_n + tn + j;
            float v = acc[i][j] + bias[n];
            if (RELU) v = fmaxf(v, 0.f);
            C[(size_t)m * N + n] = v;
        }
    }
}

// ===========================================================================
// TF32 tensor-core GEMM, cp.async 2-stage pipeline.
// C[M,N] = relu(A[M,(lda)] @ W[N,(ldb)]^T + bias)
// 256 threads = 8 warps arranged WM_ x (8/WM_); warp tile 32 x (BN_*WM_/8).
// K % 32 == 0; lda/ldb % 4 == 0; zero-padding inside [K] by caller.
// SMEM (dynamic): 2 stages x (BM_ + BN_) x 36 floats.
// ===========================================================================
#define GTK 32
#define SPAD 36

__device__ __forceinline__ uint32_t f2tf32(float f) {
    uint32_t r;
    asm("cvt.rna.tf32.f32 %0, %1;" : "=r"(r) : "f"(f));
    return r;
}

__device__ __forceinline__ void cp16(uint32_t s, const void* g) {
    asm volatile("cp.async.ca.shared.global [%0], [%1], 16;" :: "r"(s), "l"(g));
}

template <bool RELU, int BM_, int BN_, int WM_>
__global__ __launch_bounds__(256) void gemm_tf32(
    const float* __restrict__ A, const float* __restrict__ W,
    const float* __restrict__ bias, float* __restrict__ C,
    int M, int N, int K, int lda, int ldb)
{
    constexpr int WN_WARPS = 8 / WM_;
    constexpr int WTN = BN_ / WN_WARPS;     // warp tile N
    constexpr int NI  = WTN / 8;            // b-fragments per warp
    constexpr int A_IT = BM_ / 32;          // float4 loads per thread (A)
    constexpr int B_IT = BN_ / 32;          // float4 loads per thread (B)

    extern __shared__ float smx[];
    float* AsBuf = smx;                      // [2][BM_][SPAD]
    float* BsBuf = smx + 2 * BM_ * SPAD;     // [2][BN_][SPAD]

    const int tid  = threadIdx.x;
    const int lane = tid & 31;
    const int warp = tid >> 5;
    const int bm = blockIdx.y * BM_;
    const int bn = blockIdx.x * BN_;
    const int warp_m = (warp % WM_) * 32;
    const int warp_n = (warp / WM_) * WTN;
    const int g  = lane >> 2;
    const int tg = lane & 3;

    const int a_row = tid >> 3;              // 0..31
    const int a_c4  = (tid & 7) * 4;

    const uint32_t as_s = (uint32_t)__cvta_generic_to_shared(AsBuf);
    const uint32_t bs_s = (uint32_t)__cvta_generic_to_shared(BsBuf);

    float acc[2][NI][4];
#pragma unroll
    for (int mi = 0; mi < 2; mi++)
#pragma unroll
        for (int ni = 0; ni < NI; ni++)
#pragma unroll
            for (int r = 0; r < 4; r++) acc[mi][ni][r] = 0.f;

    const int nch = K / GTK;

    // issue stage loads for chunk ch into buffer (ch & 1)
    auto issue = [&](int ch) {
        const int st = ch & 1;
        const int k0 = ch * GTK;
#pragma unroll
        for (int it = 0; it < A_IT; it++) {
            int row = a_row + it * 32;
            cp16(as_s + ((st * BM_ + row) * SPAD + a_c4) * 4,
                 A + (size_t)(bm + row) * lda + k0 + a_c4);
        }
#pragma unroll
        for (int it = 0; it < B_IT; it++) {
            int row = a_row + it * 32;
            cp16(bs_s + ((st * BN_ + row) * SPAD + a_c4) * 4,
                 W + (size_t)(bn + row) * ldb + k0 + a_c4);
        }
        asm volatile("cp.async.commit_group;");
    };

    issue(0);

    for (int ch = 0; ch < nch; ch++) {
        if (ch + 1 < nch) {
            issue(ch + 1);
            asm volatile("cp.async.wait_group 1;");
        } else {
            asm volatile("cp.async.wait_group 0;");
        }
        __syncthreads();

        const float* Acur = AsBuf + (ch & 1) * BM_ * SPAD;
        const float* Bcur = BsBuf + (ch & 1) * BN_ * SPAD;

#pragma unroll
        for (int ks = 0; ks < 4; ks++) {
            const int k = ks * 8;
            uint32_t af[2][4], bf[NI][2];
#pragma unroll
            for (int mi = 0; mi < 2; mi++) {
                int r = warp_m + mi * 16 + g;
                af[mi][0] = f2tf32(Acur[r * SPAD + k + tg]);
                af[mi][1] = f2tf32(Acur[(r + 8) * SPAD + k + tg]);
                af[mi][2] = f2tf32(Acur[r * SPAD + k + 4 + tg]);
                af[mi][3] = f2tf32(Acur[(r + 8) * SPAD + k + 4 + tg]);
            }
#pragma unroll
            for (int ni = 0; ni < NI; ni++) {
                int c = warp_n + ni * 8 + g;
                bf[ni][0] = f2tf32(Bcur[c * SPAD + k + tg]);
                bf[ni][1] = f2tf32(Bcur[c * SPAD + k + 4 + tg]);
            }
#pragma unroll
            for (int mi = 0; mi < 2; mi++)
#pragma unroll
                for (int ni = 0; ni < NI; ni++) {
                    asm volatile(
                        "mma.sync.aligned.m16n8k8.row.col.f32.tf32.tf32.f32 "
                        "{%0,%1,%2,%3}, {%4,%5,%6,%7}, {%8,%9}, {%0,%1,%2,%3};"
                        : "+f"(acc[mi][ni][0]), "+f"(acc[mi][ni][1]),
                          "+f"(acc[mi][ni][2]), "+f"(acc[mi][ni][3])
                        : "r"(af[mi][0]), "r"(af[mi][1]),
                          "r"(af[mi][2]), "r"(af[mi][3]),
                          "r"(bf[ni][0]), "r"(bf[ni][1]));
                }
        }
        __syncthreads();
    }

    // ---- epilogue
#pragma unroll
    for (int mi = 0; mi < 2; mi++) {
#pragma unroll
        for (int ni = 0; ni < NI; ni++) {
            int c = bn + warp_n + ni * 8 + tg * 2;
            float b0 = bias[c], b1 = bias[c + 1];
            int r0 = bm + warp_m + mi * 16 + g;
            float v0 = acc[mi][ni][0] + b0;
            float v1 = acc[mi][ni][1] + b1;
            float v2 = acc[mi][ni][2] + b0;
            float v3 = acc[mi][ni][3] + b1;
            if (RELU) {
                v0 = fmaxf(v0, 0.f); v1 = fmaxf(v1, 0.f);
                v2 = fmaxf(v2, 0.f); v3 = fmaxf(v3, 0.f);
            }
            C[(size_t)r0 * N + c]           = v0;
            C[(size_t)r0 * N + c + 1]       = v1;
            C[(size_t)(r0 + 8) * N + c]     = v2;
            C[(size_t)(r0 + 8) * N + c + 1] = v3;
        }
    }
}

// ===========================================================================
// Repack tw0 [512][415] -> g_w0pad [512][416], pad col = 0
// ===========================================================================
__global__ __launch_bounds__(256) void repack_w0(
    const float* __restrict__ src, float* __restrict__ dst)
{
    int i = blockIdx.x * blockDim.x + threadIdx.x;
    if (i >= 512 * RSTRIDE) return;
    int row = i / RSTRIDE;
    int col = i - row * RSTRIDE;
    dst[i] = (col < RDIM) ? src[(size_t)row * RDIM + col] : 0.f;
}

// ===========================================================================
// Embedding gather (mean over 4) + interaction; 4 batch rows per block.
// ===========================================================================
#define RPB 4

__global__ __launch_bounds__(256) void embed_interact(
    const float* __restrict__ x3,
    const int* __restrict__ lS_i,
    const float* __restrict__ tables,
    float* __restrict__ R)
{
    __shared__ float T[RPB][NFEAT * 68];
    const int b0 = blockIdx.x * RPB;
    const int tid = threadIdx.x;

    if (tid < RPB * 16) {
        int r = tid >> 4, q = tid & 15;
        float4 v = *reinterpret_cast<const float4*>(
            x3 + (size_t)(b0 + r) * D_EMB + q * 4);
        *reinterpret_cast<float4*>(&T[r][q * 4]) = v;
    }

    for (int i = tid; i < RPB * N_TAB * 16; i += 256) {
        int d4 = (i & 15) * 4;
        int tt = i >> 4;
        int t  = tt % N_TAB;
        int r  = tt / N_TAB;
        int4 idx = *reinterpret_cast<const int4*>(
            lS_i + (size_t)t * (B_SZ * POOL_L) + (size_t)(b0 + r) * POOL_L);
        const float* tab = tables + (size_t)t * 100001 * D_EMB;
        float4 v0 = *reinterpret_cast<const float4*>(tab + (size_t)idx.x * D_EMB + d4);
        float4 v1 = *reinterpret_cast<const float4*>(tab + (size_t)idx.y * D_EMB + d4);
        float4 v2 = *reinterpret_cast<const float4*>(tab + (size_t)idx.z * D_EMB + d4);
        float4 v3 = *reinterpret_cast<const float4*>(tab + (size_t)idx.w * D_EMB + d4);
        float* dst = &T[r][(t + 1) * 68 + d4];
        dst[0] = (v0.x + v1.x + v2.x + v3.x) * 0.25f;
        dst[1] = (v0.y + v1.y + v2.y + v3.y) * 0.25f;
        dst[2] = (v0.z + v1.z + v2.z + v3.z) * 0.25f;
        dst[3] = (v0.w + v1.w + v2.w + v3.w) * 0.25f;
    }
    __syncthreads();

    if (tid < RPB * 16) {
        int r = tid >> 4, q = tid & 15;
        *reinterpret_cast<float4*>(R + (size_t)(b0 + r) * RSTRIDE + q * 4) =
            *reinterpret_cast<const float4*>(&T[r][q * 4]);
    }
    if (tid < RPB) R[(size_t)(b0 + tid) * RSTRIDE + RDIM] = 0.f;

    for (int ii = tid; ii < RPB * NPAIR; ii += 256) {
        int r = ii / NPAIR;
        int p = ii - r * NPAIR;
        int i = (int)((1.0f + sqrtf(1.0f + 8.0f * (float)p)) * 0.5f);
        while (i * (i - 1) / 2 > p) i--;
        while ((i + 1) * i / 2 <= p) i++;
        int j = p - i * (i - 1) / 2;

        const float4* ti = reinterpret_cast<const float4*>(&T[r][i * 68]);
        const float4* tj = reinterpret_cast<const float4*>(&T[r][j * 68]);
        float acc = 0.f;
#pragma unroll
        for (int d4 = 0; d4 < 16; d4++) {
            float4 u = ti[d4];
            float4 v = tj[d4];
            acc += u.x * v.x + u.y * v.y + u.z * v.z + u.w * v.w;
        }
        R[(size_t)(b0 + r) * RSTRIDE + D_EMB + p] = acc;
    }
}

// ===========================================================================
// Final layer: out[m] = Z[m,:256].w + b
// ===========================================================================
__global__ __launch_bounds__(256) void final_layer(
    const float* __restrict__ Z, const float* __restrict__ w,
    const float* __restrict__ bias, float* __restrict__ out, int M, int K)
{
    int warp = (blockIdx.x * blockDim.x + threadIdx.x) >> 5;
    int lane = threadIdx.x & 31;
    if (warp >= M) return;
    float acc = 0.f;
    for (int k = lane * 4; k < K; k += 128) {
        float4 z = *reinterpret_cast<const float4*>(Z + (size_t)warp * K + k);
        float4 ww = *reinterpret_cast<const float4*>(w + k);
        acc += z.x * ww.x + z.y * ww.y + z.z * ww.z + z.w * ww.w;
    }
#pragma unroll
    for (int o = 16; o; o >>= 1) acc += __shfl_xor_sync(0xFFFFFFFFu, acc, o);
    if (lane == 0) out[warp] = acc + bias[0];
}

// ===========================================================================
extern "C" void kernel_launch(void* const* d_in, const int* in_sizes, int n_in,
                              void* d_out, int out_size)
{
    (void)in_sizes; (void)n_in; (void)out_size;

    const float* dense_x = (const float*)d_in[0];
    const int*   lS_i    = (const int*)d_in[2];
    const float* emb     = (const float*)d_in[3];
    const float* bw0     = (const float*)d_in[4];
    const float* bb0     = (const float*)d_in[5];
    const float* bw1     = (const float*)d_in[6];
    const float* bb1     = (const float*)d_in[7];
    const float* bw2     = (const float*)d_in[8];
    const float* bb2     = (const float*)d_in[9];
    const float* tw0     = (const float*)d_in[10];
    const float* tb0     = (const float*)d_in[11];
    const float* tw1     = (const float*)d_in[12];
    const float* tb1     = (const float*)d_in[13];
    const float* tw2     = (const float*)d_in[14];
    const float* tb2     = (const float*)d_in[15];
    float*       out     = (float*)d_out;

    float *buf0, *buf1, *R, *w0pad;
    cudaGetSymbolAddress((void**)&buf0,  g_buf0);
    cudaGetSymbolAddress((void**)&buf1,  g_buf1);
    cudaGetSymbolAddress((void**)&R,     g_R);
    cudaGetSymbolAddress((void**)&w0pad, g_w0pad);

    dim3 blk(256);

    // dynamic SMEM sizes for the two gemm configs
    const int smem_big   = 2 * (128 + 64) * SPAD * (int)sizeof(float); // 55296
    const int smem_small = 2 * (64 + 64) * SPAD * (int)sizeof(float);  // 36864
    cudaFuncSetAttribute((const void*)gemm_tf32<true, 128, 64, 4>,
                         cudaFuncAttributeMaxDynamicSharedMemorySize, smem_big);
    cudaFuncSetAttribute((const void*)gemm_tf32<true, 64, 64, 2>,
                         cudaFuncAttributeMaxDynamicSharedMemorySize, smem_small);

    // repack tw0 early (independent)
    repack_w0<<<(512 * RSTRIDE + 255) / 256, blk>>>(tw0, w0pad);

    // layer 1: 13 -> 512 (fp32)
    gemm_bias<true><<<dim3(512 / BN, B_SZ / BM), blk>>>(dense_x, bw0, bb0, buf0, B_SZ, 512, 13);
    // layer 2: 512 -> 256
    gemm_tf32<true, 128, 64, 4><<<dim3(256 / 64, B_SZ / 128), blk, smem_big>>>(
        buf0, bw1, bb1, buf1, B_SZ, 256, 512, 512, 512);
    // layer 3: 256 -> 64 (small-N config: 128 blocks)
    gemm_tf32<true, 64, 64, 2><<<dim3(1, B_SZ / 64), blk, smem_small>>>(
        buf1, bw2, bb2, buf0, B_SZ, 64, 256, 256, 256);

    // embeddings + interaction -> R[B,416]
    embed_interact<<<B_SZ / RPB, blk>>>(buf0, lS_i, emb, R);

    // layer 4: 416 -> 512
    gemm_tf32<true, 128, 64, 4><<<dim3(512 / 64, B_SZ / 128), blk, smem_big>>>(
        R, w0pad, tb0, buf1, B_SZ, 512, RSTRIDE, RSTRIDE, RSTRIDE);
    // layer 5: 512 -> 256
    gemm_tf32<true, 128, 64, 4><<<dim3(256 / 64, B_SZ / 128), blk, smem_big>>>(
        buf1, tw1, tb1, buf0, B_SZ, 256, 512, 512, 512);

    // final 256 -> 1
    final_layer<<<(B_SZ * 32 + 255) / 256, blk>>>(buf0, tw2, tb2, out, B_SZ, 256);
}